// round 15
// baseline (speedup 1.0000x reference)
#include <cuda_runtime.h>
#include <cstdint>

#define MULC 64
#define BASE 9
#define ROW  576     // MULC*BASE
#define NP   11
#define EB   4       // edges per tile; 50000 % 4 == 0 -> ALL tiles full
#define TPB  256
#define NV   39

// ---------------------------------------------------------------------------
// Sparse structure of the dense w3j buffer (p, k_out, i_in1, j_in2). 83
// nonzeros collapsing to 39 distinct values; values are loaded from the input
// w3j buffer so numerics match the reference exactly.
// ---------------------------------------------------------------------------

#define VAL_LIST(X) \
  X( 0, 0,0,0,0) \
  X( 1, 1,1,0,1) \
  X( 2, 2,4,0,4) \
  X( 3, 3,1,1,0) \
  X( 4, 4,0,1,1) \
  X( 5, 5,4,3,1) \
  X( 6, 5,5,1,2) \
  X( 7, 5,6,1,1) \
  X( 8, 5,6,2,2) \
  X( 9, 5,6,3,3) \
  X(10, 5,7,2,3) \
  X(11, 5,8,1,1) \
  X(12, 5,8,3,3) \
  X(13, 6,1,3,4) \
  X(14, 6,2,1,5) \
  X(15, 6,1,1,6) \
  X(16, 6,2,2,6) \
  X(17, 6,3,3,6) \
  X(18, 6,3,2,7) \
  X(19, 6,1,1,8) \
  X(20, 6,3,3,8) \
  X(21, 7,4,4,0) \
  X(22, 8,1,4,3) \
  X(23, 8,2,5,1) \
  X(24, 8,1,6,1) \
  X(25, 8,2,6,2) \
  X(26, 8,3,6,3) \
  X(27, 8,3,7,2) \
  X(28, 8,1,8,1) \
  X(29, 8,3,8,3) \
  X(30, 9,0,4,4) \
  X(31,10,6,6,6) \
  X(32,10,6,7,7) \
  X(33,10,6,5,5) \
  X(34,10,6,8,8) \
  X(35,10,6,4,4) \
  X(36,10,8,7,7) \
  X(37,10,8,5,5) \
  X(38,10,4,7,5)

#define TERM_LIST(X) \
  X( 0, 0,0,0) \
  X( 1, 1,0,1) X( 1, 2,0,2) X( 1, 3,0,3) \
  X( 2, 4,0,4) X( 2, 5,0,5) X( 2, 6,0,6) X( 2, 7,0,7) X( 2, 8,0,8) \
  X( 3, 1,1,0) X( 3, 2,2,0) X( 3, 3,3,0) \
  X( 4, 0,1,1) X( 4, 0,2,2) X( 4, 0,3,3) \
  X( 5, 4,3,1) X( 5, 4,1,3) \
  X( 6, 5,1,2) X( 6, 5,2,1) \
  X( 7, 6,1,1) X( 8, 6,2,2) X( 9, 6,3,3) \
  X(10, 7,2,3) X(10, 7,3,2) \
  X(11, 8,1,1) X(12, 8,3,3) \
  X(13, 1,3,4) X(13, 3,1,4) \
  X(14, 2,1,5) X(14, 1,2,5) \
  X(15, 1,1,6) X(16, 2,2,6) X(17, 3,3,6) \
  X(18, 3,2,7) X(18, 2,3,7) \
  X(19, 1,1,8) X(20, 3,3,8) \
  X(21, 4,4,0) X(21, 5,5,0) X(21, 6,6,0) X(21, 7,7,0) X(21, 8,8,0) \
  X(22, 1,4,3) X(22, 3,4,1) \
  X(23, 2,5,1) X(23, 1,5,2) \
  X(24, 1,6,1) X(25, 2,6,2) X(26, 3,6,3) \
  X(27, 3,7,2) X(27, 2,7,3) \
  X(28, 1,8,1) X(29, 3,8,3) \
  X(30, 0,4,4) X(30, 0,5,5) X(30, 0,6,6) X(30, 0,7,7) X(30, 0,8,8) \
  X(31, 6,6,6) \
  X(32, 6,7,7) X(32, 7,7,6) X(32, 7,6,7) \
  X(33, 6,5,5) X(33, 5,5,6) X(33, 5,6,5) \
  X(34, 6,8,8) X(34, 8,8,6) X(34, 8,6,8) \
  X(35, 6,4,4) X(35, 4,4,6) X(35, 4,6,4) \
  X(36, 8,7,7) X(36, 7,8,7) X(36, 7,7,8) \
  X(37, 8,5,5) X(37, 5,8,5) X(37, 5,5,8) \
  X(38, 4,7,5) X(38, 4,5,7) X(38, 7,4,5) X(38, 5,4,7) X(38, 7,5,4) X(38, 5,7,4)

#define TILE_FLOATS (EB * ROW)          // 2304
#define TILE_BYTES  (TILE_FLOATS * 4)   // 9216

// smem: s1[2], s2[2] double-buffered inputs, so[2] outputs, 2 mbarriers
#define OFF_S1   0
#define OFF_S2   (2 * TILE_BYTES)
#define OFF_SO   (4 * TILE_BYTES)
#define OFF_MBAR (6 * TILE_BYTES)
#define SMEM_BYTES (OFF_MBAR + 16)      // 55312 -> 3 blocks/SM

#define NSM   148
#define GRID  (3 * NSM)                 // 444 persistent blocks

__device__ __forceinline__ void mbar_init(uint32_t mbar, uint32_t cnt) {
    asm volatile("mbarrier.init.shared.b64 [%0], %1;" :: "r"(mbar), "r"(cnt) : "memory");
}
__device__ __forceinline__ void mbar_expect_tx(uint32_t mbar, uint32_t bytes) {
    asm volatile("mbarrier.arrive.expect_tx.shared.b64 _, [%0], %1;"
                 :: "r"(mbar), "r"(bytes) : "memory");
}
__device__ __forceinline__ void mbar_wait(uint32_t mbar, uint32_t parity) {
    asm volatile(
        "{\n\t.reg .pred P;\n\t"
        "WAIT_%=:\n\t"
        "mbarrier.try_wait.parity.acquire.cta.shared::cta.b64 P, [%0], %1, 0x989680;\n\t"
        "@P bra DONE_%=;\n\t"
        "bra WAIT_%=;\n\t"
        "DONE_%=:\n\t}"
        :: "r"(mbar), "r"(parity) : "memory");
}
// streaming (evict_first) policy: every byte is touched exactly once
__device__ __forceinline__ uint64_t policy_stream() {
    uint64_t pol;
    asm volatile("createpolicy.fractional.L2::evict_first.b64 %0, 1.0;" : "=l"(pol));
    return pol;
}
__device__ __forceinline__ void bulk_g2s(uint32_t sdst, const void* gsrc,
                                         uint32_t bytes, uint32_t mbar, uint64_t pol) {
    asm volatile(
        "cp.async.bulk.shared::cta.global.mbarrier::complete_tx::bytes.L2::cache_hint"
        " [%0], [%1], %2, [%3], %4;"
        :: "r"(sdst), "l"(gsrc), "r"(bytes), "r"(mbar), "l"(pol) : "memory");
}
__device__ __forceinline__ void bulk_s2g(void* gdst, uint32_t ssrc, uint32_t bytes,
                                         uint64_t pol) {
    asm volatile(
        "cp.async.bulk.global.shared::cta.bulk_group.L2::cache_hint [%0], [%1], %2, %3;"
        :: "l"(gdst), "r"(ssrc), "r"(bytes), "l"(pol) : "memory");
}
__device__ __forceinline__ void bulk_commit() {
    asm volatile("cp.async.bulk.commit_group;" ::: "memory");
}
__device__ __forceinline__ void bulk_wait_read1() {
    asm volatile("cp.async.bulk.wait_group.read 1;" ::: "memory");
}
__device__ __forceinline__ void bulk_wait_all() {
    asm volatile("cp.async.bulk.wait_group 0;" ::: "memory");
}
__device__ __forceinline__ void fence_async() {
    asm volatile("fence.proxy.async.shared::cta;" ::: "memory");
}

__global__ void __launch_bounds__(TPB, 3)
tp_kernel(const float* __restrict__ x1, const float* __restrict__ x2,
          const float* __restrict__ wts, const float* __restrict__ w3j,
          float* __restrict__ out, int ntiles)
{
    extern __shared__ __align__(16) char smem[];
    float* s1f = (float*)(smem + OFF_S1);
    float* s2f = (float*)(smem + OFF_S2);
    float* sof = (float*)(smem + OFF_SO);

    const uint32_t sbase = (uint32_t)__cvta_generic_to_shared(smem);
    const uint32_t mbar0 = sbase + OFF_MBAR;

    const int tid = threadIdx.x;
    const int u   = tid & 63;
    const int e   = tid >> 6;             // 0..3 : tiles are ALWAYS full
    const int item = e * ROW + u * BASE;  // constant across tiles

    if (tid == 0) { mbar_init(mbar0, 1); mbar_init(mbar0 + 8, 1); }
    __syncthreads();

    const int G = gridDim.x;
    const uint64_t pol = policy_stream();

    // ---- prologue: kick off first tile's TMA ----
    int tile = blockIdx.x;
    if (tid == 0 && tile < ntiles) {
        mbar_expect_tx(mbar0, 2 * TILE_BYTES);
        bulk_g2s(sbase + OFF_S1, x1 + (size_t)tile * TILE_FLOATS, TILE_BYTES, mbar0, pol);
        bulk_g2s(sbase + OFF_S2, x2 + (size_t)tile * TILE_FLOATS, TILE_BYTES, mbar0, pol);
    }

    // ---- fold coefficients under the in-flight TMA ----
    float cw[NV];
    {
        float wv[NP];
        #pragma unroll
        for (int p = 0; p < NP; ++p) wv[p] = wts[u * NP + p];
#define LOADV(v, p, k, i, j) cw[v] = wv[p] * w3j[(p)*729 + (k)*81 + (i)*9 + (j)];
        VAL_LIST(LOADV)
#undef LOADV
    }

    int buf = 0, sb = 0;
    int ph0 = 0, ph1 = 0;
    for (; tile < ntiles; tile += G) {
        // ---- prefetch next tile into the other input buffer ----
        const int nxt = tile + G;
        if (tid == 0) {
            if (nxt < ntiles) {
                const uint32_t mb = mbar0 + (uint32_t)(buf ^ 1) * 8u;
                mbar_expect_tx(mb, 2 * TILE_BYTES);
                bulk_g2s(sbase + OFF_S1 + (uint32_t)(buf ^ 1) * TILE_BYTES,
                         x1 + (size_t)nxt * TILE_FLOATS, TILE_BYTES, mb, pol);
                bulk_g2s(sbase + OFF_S2 + (uint32_t)(buf ^ 1) * TILE_BYTES,
                         x2 + (size_t)nxt * TILE_FLOATS, TILE_BYTES, mb, pol);
            }
            // drain the store issued 2 iterations ago (guards so[sb]) while
            // the other warps head into the barrier
            bulk_wait_read1();
        }

        // ---- warp 0 performs the acquire-wait; bar.sync propagates the
        //      ordering to the other 7 warps (they sleep at BAR, not polling)
        if (tid < 32) {
            const uint32_t mb = mbar0 + (uint32_t)buf * 8u;
            mbar_wait(mb, (buf == 0) ? ph0 : ph1);
        }
        if (buf == 0) ph0 ^= 1; else ph1 ^= 1;
        __syncthreads();

        // ---- compute: one (e,u) item per thread, tiles always full ----
        {
            const float* p1 = s1f + buf * TILE_FLOATS + item;
            const float* p2 = s2f + buf * TILE_FLOATS + item;
            float a[BASE], b[BASE], acc[BASE];
            #pragma unroll
            for (int q = 0; q < BASE; ++q) {
                a[q] = p1[q];
                b[q] = p2[q];
                acc[q] = 0.0f;
            }
#define DOFMA(v, k, i, j) acc[k] = fmaf(cw[v], a[i] * b[j], acc[k]);
            TERM_LIST(DOFMA)
#undef DOFMA
            float* po = sof + sb * TILE_FLOATS + item;
            #pragma unroll
            for (int q = 0; q < BASE; ++q) po[q] = acc[q];
        }
        __syncthreads();

        // ---- async bulk store (off the critical path) ----
        if (tid == 0) {
            fence_async();
            bulk_s2g(out + (size_t)tile * TILE_FLOATS,
                     sbase + OFF_SO + (uint32_t)sb * TILE_BYTES, TILE_BYTES, pol);
            bulk_commit();
        }

        buf ^= 1; sb ^= 1;
    }

    // ---- drain outstanding stores before smem dies with the block ----
    if (tid == 0) bulk_wait_all();
}

extern "C" void kernel_launch(void* const* d_in, const int* in_sizes, int n_in,
                              void* d_out, int out_size)
{
    const float* x1  = (const float*)d_in[0];
    const float* x2  = (const float*)d_in[1];
    const float* wts = (const float*)d_in[2];
    const float* w3j = (const float*)d_in[3];
    float* out = (float*)d_out;

    const int nz     = in_sizes[0] / ROW;   // 50000
    const int ntiles = nz / EB;             // 12500, exact (50000 % 4 == 0)

    cudaFuncSetAttribute(tp_kernel, cudaFuncAttributeMaxDynamicSharedMemorySize,
                         SMEM_BYTES);
    tp_kernel<<<GRID, TPB, SMEM_BYTES>>>(x1, x2, wts, w3j, out, ntiles);
}

// round 16
// speedup vs baseline: 1.0218x; 1.0218x over previous
#include <cuda_runtime.h>
#include <cstdint>

#define MULC 64
#define BASE 9
#define ROW  576     // MULC*BASE
#define NP   11
#define EB   4       // edges per tile; 50000 % 4 == 0 -> ALL tiles full
#define TPB  256
#define NV   39

// ---------------------------------------------------------------------------
// Sparse structure of the dense w3j buffer (p, k_out, i_in1, j_in2). 83
// nonzeros collapsing to 39 distinct values; values are loaded from the input
// w3j buffer so numerics match the reference exactly.
// ---------------------------------------------------------------------------

#define VAL_LIST(X) \
  X( 0, 0,0,0,0) \
  X( 1, 1,1,0,1) \
  X( 2, 2,4,0,4) \
  X( 3, 3,1,1,0) \
  X( 4, 4,0,1,1) \
  X( 5, 5,4,3,1) \
  X( 6, 5,5,1,2) \
  X( 7, 5,6,1,1) \
  X( 8, 5,6,2,2) \
  X( 9, 5,6,3,3) \
  X(10, 5,7,2,3) \
  X(11, 5,8,1,1) \
  X(12, 5,8,3,3) \
  X(13, 6,1,3,4) \
  X(14, 6,2,1,5) \
  X(15, 6,1,1,6) \
  X(16, 6,2,2,6) \
  X(17, 6,3,3,6) \
  X(18, 6,3,2,7) \
  X(19, 6,1,1,8) \
  X(20, 6,3,3,8) \
  X(21, 7,4,4,0) \
  X(22, 8,1,4,3) \
  X(23, 8,2,5,1) \
  X(24, 8,1,6,1) \
  X(25, 8,2,6,2) \
  X(26, 8,3,6,3) \
  X(27, 8,3,7,2) \
  X(28, 8,1,8,1) \
  X(29, 8,3,8,3) \
  X(30, 9,0,4,4) \
  X(31,10,6,6,6) \
  X(32,10,6,7,7) \
  X(33,10,6,5,5) \
  X(34,10,6,8,8) \
  X(35,10,6,4,4) \
  X(36,10,8,7,7) \
  X(37,10,8,5,5) \
  X(38,10,4,7,5)

#define TERM_LIST(X) \
  X( 0, 0,0,0) \
  X( 1, 1,0,1) X( 1, 2,0,2) X( 1, 3,0,3) \
  X( 2, 4,0,4) X( 2, 5,0,5) X( 2, 6,0,6) X( 2, 7,0,7) X( 2, 8,0,8) \
  X( 3, 1,1,0) X( 3, 2,2,0) X( 3, 3,3,0) \
  X( 4, 0,1,1) X( 4, 0,2,2) X( 4, 0,3,3) \
  X( 5, 4,3,1) X( 5, 4,1,3) \
  X( 6, 5,1,2) X( 6, 5,2,1) \
  X( 7, 6,1,1) X( 8, 6,2,2) X( 9, 6,3,3) \
  X(10, 7,2,3) X(10, 7,3,2) \
  X(11, 8,1,1) X(12, 8,3,3) \
  X(13, 1,3,4) X(13, 3,1,4) \
  X(14, 2,1,5) X(14, 1,2,5) \
  X(15, 1,1,6) X(16, 2,2,6) X(17, 3,3,6) \
  X(18, 3,2,7) X(18, 2,3,7) \
  X(19, 1,1,8) X(20, 3,3,8) \
  X(21, 4,4,0) X(21, 5,5,0) X(21, 6,6,0) X(21, 7,7,0) X(21, 8,8,0) \
  X(22, 1,4,3) X(22, 3,4,1) \
  X(23, 2,5,1) X(23, 1,5,2) \
  X(24, 1,6,1) X(25, 2,6,2) X(26, 3,6,3) \
  X(27, 3,7,2) X(27, 2,7,3) \
  X(28, 1,8,1) X(29, 3,8,3) \
  X(30, 0,4,4) X(30, 0,5,5) X(30, 0,6,6) X(30, 0,7,7) X(30, 0,8,8) \
  X(31, 6,6,6) \
  X(32, 6,7,7) X(32, 7,7,6) X(32, 7,6,7) \
  X(33, 6,5,5) X(33, 5,5,6) X(33, 5,6,5) \
  X(34, 6,8,8) X(34, 8,8,6) X(34, 8,6,8) \
  X(35, 6,4,4) X(35, 4,4,6) X(35, 4,6,4) \
  X(36, 8,7,7) X(36, 7,8,7) X(36, 7,7,8) \
  X(37, 8,5,5) X(37, 5,8,5) X(37, 5,5,8) \
  X(38, 4,7,5) X(38, 4,5,7) X(38, 7,4,5) X(38, 5,4,7) X(38, 7,5,4) X(38, 5,7,4)

#define TILE_FLOATS (EB * ROW)          // 2304
#define TILE_BYTES  (TILE_FLOATS * 4)   // 9216

// smem: s1[2], s2[2] double-buffered inputs, so[2] outputs, 2 mbarriers
#define OFF_S1   0
#define OFF_S2   (2 * TILE_BYTES)
#define OFF_SO   (4 * TILE_BYTES)
#define OFF_MBAR (6 * TILE_BYTES)
#define SMEM_BYTES (OFF_MBAR + 16)      // 55312 -> 3 blocks/SM

#define NSM   148
#define GRID  (3 * NSM)                 // 444 persistent blocks

__device__ __forceinline__ void mbar_init(uint32_t mbar, uint32_t cnt) {
    asm volatile("mbarrier.init.shared.b64 [%0], %1;" :: "r"(mbar), "r"(cnt) : "memory");
}
__device__ __forceinline__ void mbar_expect_tx(uint32_t mbar, uint32_t bytes) {
    asm volatile("mbarrier.arrive.expect_tx.shared.b64 _, [%0], %1;"
                 :: "r"(mbar), "r"(bytes) : "memory");
}
__device__ __forceinline__ void mbar_wait(uint32_t mbar, uint32_t parity) {
    asm volatile(
        "{\n\t.reg .pred P;\n\t"
        "WAIT_%=:\n\t"
        "mbarrier.try_wait.parity.acquire.cta.shared::cta.b64 P, [%0], %1, 0x989680;\n\t"
        "@P bra DONE_%=;\n\t"
        "bra WAIT_%=;\n\t"
        "DONE_%=:\n\t}"
        :: "r"(mbar), "r"(parity) : "memory");
}
// streaming (evict_first) policy: every byte is touched exactly once
__device__ __forceinline__ uint64_t policy_stream() {
    uint64_t pol;
    asm volatile("createpolicy.fractional.L2::evict_first.b64 %0, 1.0;" : "=l"(pol));
    return pol;
}
__device__ __forceinline__ void bulk_g2s(uint32_t sdst, const void* gsrc,
                                         uint32_t bytes, uint32_t mbar, uint64_t pol) {
    asm volatile(
        "cp.async.bulk.shared::cta.global.mbarrier::complete_tx::bytes.L2::cache_hint"
        " [%0], [%1], %2, [%3], %4;"
        :: "r"(sdst), "l"(gsrc), "r"(bytes), "r"(mbar), "l"(pol) : "memory");
}
__device__ __forceinline__ void bulk_s2g(void* gdst, uint32_t ssrc, uint32_t bytes,
                                         uint64_t pol) {
    asm volatile(
        "cp.async.bulk.global.shared::cta.bulk_group.L2::cache_hint [%0], [%1], %2, %3;"
        :: "l"(gdst), "r"(ssrc), "r"(bytes), "l"(pol) : "memory");
}
__device__ __forceinline__ void bulk_commit() {
    asm volatile("cp.async.bulk.commit_group;" ::: "memory");
}
__device__ __forceinline__ void bulk_wait_read1() {
    asm volatile("cp.async.bulk.wait_group.read 1;" ::: "memory");
}
__device__ __forceinline__ void bulk_wait_all() {
    asm volatile("cp.async.bulk.wait_group 0;" ::: "memory");
}
__device__ __forceinline__ void fence_async() {
    asm volatile("fence.proxy.async.shared::cta;" ::: "memory");
}

__global__ void __launch_bounds__(TPB, 3)
tp_kernel(const float* __restrict__ x1, const float* __restrict__ x2,
          const float* __restrict__ wts, const float* __restrict__ w3j,
          float* __restrict__ out, int ntiles)
{
    extern __shared__ __align__(16) char smem[];
    float* s1f = (float*)(smem + OFF_S1);
    float* s2f = (float*)(smem + OFF_S2);
    float* sof = (float*)(smem + OFF_SO);

    const uint32_t sbase = (uint32_t)__cvta_generic_to_shared(smem);
    const uint32_t mbar0 = sbase + OFF_MBAR;

    const int tid = threadIdx.x;
    const int u   = tid & 63;
    const int e   = tid >> 6;             // 0..3 : tiles are ALWAYS full
    const int item = e * ROW + u * BASE;  // constant across tiles

    if (tid == 0) { mbar_init(mbar0, 1); mbar_init(mbar0 + 8, 1); }
    __syncthreads();

    const int G = gridDim.x;
    const uint64_t pol = policy_stream();

    // ---- prologue: kick off first tile's TMA ----
    int tile = blockIdx.x;
    if (tid == 0 && tile < ntiles) {
        mbar_expect_tx(mbar0, 2 * TILE_BYTES);
        bulk_g2s(sbase + OFF_S1, x1 + (size_t)tile * TILE_FLOATS, TILE_BYTES, mbar0, pol);
        bulk_g2s(sbase + OFF_S2, x2 + (size_t)tile * TILE_FLOATS, TILE_BYTES, mbar0, pol);
    }

    // ---- fold coefficients under the in-flight TMA ----
    float cw[NV];
    {
        float wv[NP];
        #pragma unroll
        for (int p = 0; p < NP; ++p) wv[p] = wts[u * NP + p];
#define LOADV(v, p, k, i, j) cw[v] = wv[p] * w3j[(p)*729 + (k)*81 + (i)*9 + (j)];
        VAL_LIST(LOADV)
#undef LOADV
    }

    int buf = 0, sb = 0;
    int ph0 = 0, ph1 = 0;
    for (; tile < ntiles; tile += G) {
        // ---- prefetch next tile into the other input buffer ----
        const int nxt = tile + G;
        if (tid == 0) {
            if (nxt < ntiles) {
                const uint32_t mb = mbar0 + (uint32_t)(buf ^ 1) * 8u;
                mbar_expect_tx(mb, 2 * TILE_BYTES);
                bulk_g2s(sbase + OFF_S1 + (uint32_t)(buf ^ 1) * TILE_BYTES,
                         x1 + (size_t)nxt * TILE_FLOATS, TILE_BYTES, mb, pol);
                bulk_g2s(sbase + OFF_S2 + (uint32_t)(buf ^ 1) * TILE_BYTES,
                         x2 + (size_t)nxt * TILE_FLOATS, TILE_BYTES, mb, pol);
            }
            // drain the store issued 2 iterations ago (guards so[sb]) while
            // the other warps head into the barrier
            bulk_wait_read1();
        }

        // ---- warp 0 performs the acquire-wait; bar.sync propagates the
        //      ordering to the other 7 warps (they sleep at BAR, not polling)
        if (tid < 32) {
            const uint32_t mb = mbar0 + (uint32_t)buf * 8u;
            mbar_wait(mb, (buf == 0) ? ph0 : ph1);
        }
        if (buf == 0) ph0 ^= 1; else ph1 ^= 1;
        __syncthreads();

        // ---- compute: one (e,u) item per thread, tiles always full ----
        {
            const float* p1 = s1f + buf * TILE_FLOATS + item;
            const float* p2 = s2f + buf * TILE_FLOATS + item;
            float a[BASE], b[BASE], acc[BASE];
            #pragma unroll
            for (int q = 0; q < BASE; ++q) {
                a[q] = p1[q];
                b[q] = p2[q];
                acc[q] = 0.0f;
            }
#define DOFMA(v, k, i, j) acc[k] = fmaf(cw[v], a[i] * b[j], acc[k]);
            TERM_LIST(DOFMA)
#undef DOFMA
            float* po = sof + sb * TILE_FLOATS + item;
            #pragma unroll
            for (int q = 0; q < BASE; ++q) po[q] = acc[q];
        }
        __syncthreads();

        // ---- async bulk store (off the critical path) ----
        if (tid == 0) {
            fence_async();
            bulk_s2g(out + (size_t)tile * TILE_FLOATS,
                     sbase + OFF_SO + (uint32_t)sb * TILE_BYTES, TILE_BYTES, pol);
            bulk_commit();
        }

        buf ^= 1; sb ^= 1;
    }

    // ---- drain outstanding stores before smem dies with the block ----
    if (tid == 0) bulk_wait_all();
}

extern "C" void kernel_launch(void* const* d_in, const int* in_sizes, int n_in,
                              void* d_out, int out_size)
{
    const float* x1  = (const float*)d_in[0];
    const float* x2  = (const float*)d_in[1];
    const float* wts = (const float*)d_in[2];
    const float* w3j = (const float*)d_in[3];
    float* out = (float*)d_out;

    const int nz     = in_sizes[0] / ROW;   // 50000
    const int ntiles = nz / EB;             // 12500, exact (50000 % 4 == 0)

    cudaFuncSetAttribute(tp_kernel, cudaFuncAttributeMaxDynamicSharedMemorySize,
                         SMEM_BYTES);
    tp_kernel<<<GRID, TPB, SMEM_BYTES>>>(x1, x2, wts, w3j, out, ntiles);
}